// round 1
// baseline (speedup 1.0000x reference)
#include <cuda_runtime.h>
#include <math.h>

// Problem constants
#define BATCH    256
#define LOOKBACK 4096
#define SEG      32
#define DD       256          // embedding dim D
#define NSEG     128          // N = LOOKBACK/SEG
#define ROWS     32768        // B*N
#define DIM      257          // Lorentz dim D+1
#define TILE_R   8            // rows per block tile
#define TILES    (ROWS / TILE_R)   // 4096

// SMEM layout (floats):
//   Wsm : 4 * 32 * 257   (W[s][k][d], k-stride padded to 257 -> conflict free)
//   xs  : 4 * 8 * 32     (x tile staging)
//   hb  : 8 * 4 * 257    (z transpose buffer)
//   bsm : 4 * 256        (biases)
#define WSM_FLOATS (4 * 32 * 257)
#define XS_FLOATS  (4 * TILE_R * SEG)
#define HB_FLOATS  (TILE_R * 4 * DIM)
#define BS_FLOATS  (4 * 256)
#define SMEM_FLOATS (WSM_FLOATS + XS_FLOATS + HB_FLOATS + BS_FLOATS)
#define SMEM_BYTES (SMEM_FLOATS * 4)

extern __shared__ float smem[];

__device__ __forceinline__ float wredsum(float v) {
    v += __shfl_xor_sync(0xffffffffu, v, 16);
    v += __shfl_xor_sync(0xffffffffu, v, 8);
    v += __shfl_xor_sync(0xffffffffu, v, 4);
    v += __shfl_xor_sync(0xffffffffu, v, 2);
    v += __shfl_xor_sync(0xffffffffu, v, 1);
    return v;
}

__global__ __launch_bounds__(256, 1)
void splm_fused_kernel(const float* __restrict__ xt, const float* __restrict__ xc,
                       const float* __restrict__ xf, const float* __restrict__ xr,
                       const float* __restrict__ W0, const float* __restrict__ b0,
                       const float* __restrict__ W1, const float* __restrict__ b1,
                       const float* __restrict__ W2, const float* __restrict__ b2,
                       const float* __restrict__ W3, const float* __restrict__ b3,
                       const float* __restrict__ esp, const float* __restrict__ lwp,
                       float* __restrict__ out)
{
    float* Wsm = smem;
    float* xs  = smem + WSM_FLOATS;
    float* hb  = xs + XS_FLOATS;
    float* bsm = hb + HB_FLOATS;

    const int tid = threadIdx.x;
    const int w = tid >> 5;     // warp id 0..7
    const int l = tid & 31;     // lane

    const float* Wg[4] = {W0, W1, W2, W3};
    const float* bg[4] = {b0, b1, b2, b3};
    const float* xg[4] = {xt, xc, xf, xr};

    // ---- Stage W (transposed, padded) and biases once per block ----
    #pragma unroll
    for (int s = 0; s < 4; s++) {
        const float* Wp = Wg[s];
        for (int i = tid; i < DD * SEG; i += 256) {
            int d = i >> 5, k = i & 31;
            Wsm[(s * 32 + k) * 257 + d] = Wp[i];
        }
        bsm[s * 256 + tid] = bg[s][tid];
    }

    // ---- Scalars (replicated per thread) ----
    const float es = *esp;
    const float ta = tanhf(es);
    const float taa = fabsf(ta);
    float lw0 = lwp[0], lw1 = lwp[1], lw2 = lwp[2], lw3 = lwp[3];
    float mxw = fmaxf(fmaxf(lw0, lw1), fmaxf(lw2, lw3));
    float e0 = expf(lw0 - mxw), e1 = expf(lw1 - mxw);
    float e2 = expf(lw2 - mxw), e3 = expf(lw3 - mxw);
    float esum = e0 + e1 + e2 + e3;
    float wgt[4] = {e0 / esum, e1 / esum, e2 / esum, e3 / esum};

    __syncthreads();

    float bsv[4];
    #pragma unroll
    for (int s = 0; s < 4; s++) bsv[s] = bsm[s * 256 + tid];

    for (int tile = blockIdx.x; tile < TILES; tile += gridDim.x) {
        __syncthreads();   // protect xs / hb reuse across tiles

        // ---- Stage x tile: 4 series x 8 rows x 32 segs ----
        #pragma unroll
        for (int i = tid; i < 4 * TILE_R * SEG; i += 256) {
            int s = i >> 8, rem = i & 255;
            xs[i] = xg[s][tile * (TILE_R * SEG) + rem];
        }
        __syncthreads();

        // ---- Encode: thread tid owns output dim d = tid for all 4 series, 8 rows ----
        float acc[4][TILE_R];
        #pragma unroll
        for (int s = 0; s < 4; s++)
            #pragma unroll
            for (int row = 0; row < TILE_R; row++)
                acc[s][row] = bsv[s];

        #pragma unroll
        for (int kc = 0; kc < 4; kc++) {
            float wv[4][8];
            #pragma unroll
            for (int s = 0; s < 4; s++)
                #pragma unroll
                for (int kk = 0; kk < 8; kk++)
                    wv[s][kk] = Wsm[(s * 32 + kc * 8 + kk) * 257 + tid];

            #pragma unroll
            for (int row = 0; row < TILE_R; row++) {
                #pragma unroll
                for (int s = 0; s < 4; s++) {
                    const float* xrow = &xs[(s * TILE_R + row) * SEG + kc * 8];
                    float4 xa = *(const float4*)(xrow);
                    float4 xb = *(const float4*)(xrow + 4);
                    float a = acc[s][row];
                    a = fmaf(wv[s][0], xa.x, a);
                    a = fmaf(wv[s][1], xa.y, a);
                    a = fmaf(wv[s][2], xa.z, a);
                    a = fmaf(wv[s][3], xa.w, a);
                    a = fmaf(wv[s][4], xb.x, a);
                    a = fmaf(wv[s][5], xb.y, a);
                    a = fmaf(wv[s][6], xb.z, a);
                    a = fmaf(wv[s][7], xb.w, a);
                    acc[s][row] = a;
                }
            }
        }

        // z -> transpose buffer
        #pragma unroll
        for (int row = 0; row < TILE_R; row++)
            #pragma unroll
            for (int s = 0; s < 4; s++)
                hb[(row * 4 + s) * DIM + 1 + tid] = acc[s][row];
        __syncthreads();

        // ================= per-warp: row r = tile*8 + w =================
        const int r = tile * TILE_R + w;

        // ---- Load z, compute hyperbolic points ----
        float sP[4][8];   // spatial components, dim = l + 32*j (0..255 -> Lorentz 1..256)
        float tP[4];      // time components (replicated in all lanes)
        float ss[4];
        #pragma unroll
        for (int s = 0; s < 4; s++) {
            float lo = 0.f;
            #pragma unroll
            for (int j = 0; j < 8; j++) {
                float z = hb[(w * 4 + s) * DIM + 1 + l + 32 * j];
                sP[s][j] = z;
                lo = fmaf(z, z, lo);
            }
            ss[s] = lo;
        }
        #pragma unroll
        for (int s = 0; s < 4; s++) ss[s] = wredsum(ss[s]);

        #pragma unroll
        for (int s = 0; s < 4; s++) {
            float zn = sqrtf(ss[s]);
            float n  = taa * zn;
            float s1 = ta * fminf(n, 1.5f) / fmaxf(n, 1e-8f);
            float nn = fabsf(s1) * zn;            // ||v||
            float ns = fmaxf(nn, 1e-9f);
            float sh = sinhf(nn);
            float F  = s1 * sh / ns;              // xr = F * z
            float sx = sh * nn / ns;              // sqrt(sum xr^2)
            float x0v = sqrtf(1.f + sx * sx);     // projx time component
            tP[s] = x0v;
            float* hp = out + (size_t)s * ((size_t)ROWS * DIM) + (size_t)r * DIM;
            #pragma unroll
            for (int j = 0; j < 8; j++) {
                float v = sP[s][j] * F;
                sP[s][j] = v;
                hp[1 + l + 32 * j] = v;
            }
            if (l == 0) hp[0] = x0v;
        }

        // ---- Fusion init: t0 = logmap(origin, pts); wt = clip(sum w*t0, 2); mean ----
        float S[4];
        #pragma unroll
        for (int c = 0; c < 4; c++) {
            float lo = 0.f;
            #pragma unroll
            for (int j = 0; j < 8; j++) lo = fmaf(sP[c][j], sP[c][j], lo);
            S[c] = lo;
        }
        #pragma unroll
        for (int c = 0; c < 4; c++) S[c] = wredsum(S[c]);

        float wt_t = 0.f, wt_s[8];
        #pragma unroll
        for (int j = 0; j < 8; j++) wt_s[j] = 0.f;
        #pragma unroll
        for (int c = 0; c < 4; c++) {
            float alpha = fmaxf(tP[c], 1.0f + 1e-7f);
            float dist  = acoshf(alpha);
            float ut    = tP[c] - alpha;
            float un2   = fmaxf(S[c] - ut * ut, 1e-12f);
            float g     = dist / sqrtf(un2);
            float wg    = wgt[c] * g;
            wt_t = fmaf(wg, ut, wt_t);
            #pragma unroll
            for (int j = 0; j < 8; j++) wt_s[j] = fmaf(wg, sP[c][j], wt_s[j]);
        }
        float Ssp = 0.f;
        #pragma unroll
        for (int j = 0; j < 8; j++) Ssp = fmaf(wt_s[j], wt_s[j], Ssp);
        Ssp = wredsum(Ssp);
        {
            float nrm = sqrtf(Ssp + wt_t * wt_t);
            float cs  = fminf(nrm, 2.0f) / fmaxf(nrm, 1e-12f);
            float S2  = cs * cs * Ssp;            // ||clipped spatial||^2
            float nn  = sqrtf(S2);
            float ns  = fmaxf(nn, 1e-9f);
            float sh  = sinhf(nn);
            float fac = cs * sh / ns;
            #pragma unroll
            for (int j = 0; j < 8; j++) wt_s[j] *= fac;   // becomes mean spatial
            // time from projx
            float sx = sh * nn / ns;
            wt_t = sqrtf(1.f + sx * sx);                  // becomes mean time
        }
        float sm[8], tm;
        #pragma unroll
        for (int j = 0; j < 8; j++) sm[j] = wt_s[j];
        tm = wt_t;

        // ---- 5 Karcher iterations ----
        for (int it = 0; it < 5; it++) {
            // R1: spatial dot(mean, p_c)
            float dl[4];
            #pragma unroll
            for (int c = 0; c < 4; c++) {
                float lo = 0.f;
                #pragma unroll
                for (int j = 0; j < 8; j++) lo = fmaf(sm[j], sP[c][j], lo);
                dl[c] = lo;
            }
            #pragma unroll
            for (int c = 0; c < 4; c++) dl[c] = wredsum(dl[c]);

            float alpha[4], dist[4];
            #pragma unroll
            for (int c = 0; c < 4; c++) {
                alpha[c] = fmaxf(tm * tP[c] - dl[c], 1.0f + 1e-7f);  // -mink(mean,p)
                dist[c]  = acoshf(alpha[c]);
            }

            // R2: mink(u,u) pieces
            float us[4][8], U2[4];
            #pragma unroll
            for (int c = 0; c < 4; c++) {
                float lo = 0.f;
                #pragma unroll
                for (int j = 0; j < 8; j++) {
                    float u = fmaf(-alpha[c], sm[j], sP[c][j]);
                    us[c][j] = u;
                    lo = fmaf(u, u, lo);
                }
                U2[c] = lo;
            }
            #pragma unroll
            for (int c = 0; c < 4; c++) U2[c] = wredsum(U2[c]);

            float wv_t = 0.f, wv_s[8];
            #pragma unroll
            for (int j = 0; j < 8; j++) wv_s[j] = 0.f;
            #pragma unroll
            for (int c = 0; c < 4; c++) {
                float ut  = tP[c] - alpha[c] * tm;
                float un2 = fmaxf(U2[c] - ut * ut, 1e-12f);
                float g   = dist[c] / sqrtf(un2);
                float wg  = wgt[c] * g;
                wv_t = fmaf(wg, ut, wv_t);
                #pragma unroll
                for (int j = 0; j < 8; j++) wv_s[j] = fmaf(wg, us[c][j], wv_s[j]);
            }

            // R3: one reduction gives both Euclid and Minkowski norms of wv
            float Sp = 0.f;
            #pragma unroll
            for (int j = 0; j < 8; j++) Sp = fmaf(wv_s[j], wv_s[j], Sp);
            Sp = wredsum(Sp);

            float nrm = sqrtf(Sp + wv_t * wv_t);
            float cs  = fminf(nrm, 2.0f) / fmaxf(nrm, 1e-12f);
            float q   = 0.1f * cs;                      // expmap gets 0.1 * clipped wv
            float mk  = fmaxf(q * q * (Sp - wv_t * wv_t), 1e-12f);  // mink(uu,uu)
            float th  = sqrtf(mk);
            float ch  = coshf(th);
            float shh = sinhf(th);
            float coef = shh / th;                      // sinh(th)/un, un = th
            float cq = coef * q;
            #pragma unroll
            for (int j = 0; j < 8; j++) sm[j] = fmaf(cq, wv_s[j], ch * sm[j]);

            // R4: projx time component
            float Ssm = 0.f;
            #pragma unroll
            for (int j = 0; j < 8; j++) Ssm = fmaf(sm[j], sm[j], Ssm);
            Ssm = wredsum(Ssm);
            tm = sqrtf(1.f + Ssm);
        }

        // ---- Write combined ----
        float* cp = out + 4 * ((size_t)ROWS * DIM) + (size_t)r * DIM;
        #pragma unroll
        for (int j = 0; j < 8; j++) cp[1 + l + 32 * j] = sm[j];
        if (l == 0) cp[0] = tm;
    }
}

extern "C" void kernel_launch(void* const* d_in, const int* in_sizes, int n_in,
                              void* d_out, int out_size) {
    (void)in_sizes; (void)n_in; (void)out_size;
    const float* xt = (const float*)d_in[0];
    const float* xc = (const float*)d_in[1];
    const float* xf = (const float*)d_in[2];
    const float* xr = (const float*)d_in[3];
    const float* W0 = (const float*)d_in[4];
    const float* b0 = (const float*)d_in[5];
    const float* W1 = (const float*)d_in[6];
    const float* b1 = (const float*)d_in[7];
    const float* W2 = (const float*)d_in[8];
    const float* b2 = (const float*)d_in[9];
    const float* W3 = (const float*)d_in[10];
    const float* b3 = (const float*)d_in[11];
    const float* es = (const float*)d_in[12];
    const float* lw = (const float*)d_in[13];
    float* out = (float*)d_out;

    static_assert(SMEM_BYTES < 228 * 1024, "smem overflow");
    cudaFuncSetAttribute(splm_fused_kernel,
                         cudaFuncAttributeMaxDynamicSharedMemorySize, SMEM_BYTES);

    int nsm = 148;
    cudaDeviceGetAttribute(&nsm, cudaDevAttrMultiProcessorCount, 0);
    if (nsm <= 0) nsm = 148;

    splm_fused_kernel<<<nsm, 256, SMEM_BYTES>>>(xt, xc, xf, xr,
                                                W0, b0, W1, b1, W2, b2, W3, b3,
                                                es, lw, out);
}

// round 2
// speedup vs baseline: 1.4993x; 1.4993x over previous
#include <cuda_runtime.h>
#include <math.h>

// Problem constants
#define BATCH    256
#define LOOKBACK 4096
#define SEG      32
#define DD       256          // embedding dim D
#define ROWS     32768        // B*N
#define DIM      257          // Lorentz dim D+1

// ---------------- Kernel 1: encode + hyperbolic ----------------
// One series per block. W for that series lives in 32 registers per thread
// (thread owns output dim d = tid). 16 rows per tile.
#define TILE1  16
#define TILES1 (ROWS / TILE1)   // 2048

__device__ __forceinline__ float wredsum(float v) {
    v += __shfl_xor_sync(0xffffffffu, v, 16);
    v += __shfl_xor_sync(0xffffffffu, v, 8);
    v += __shfl_xor_sync(0xffffffffu, v, 4);
    v += __shfl_xor_sync(0xffffffffu, v, 2);
    v += __shfl_xor_sync(0xffffffffu, v, 1);
    return v;
}

__global__ __launch_bounds__(256, 2)
void encode_hyp_kernel(const float* __restrict__ xt, const float* __restrict__ xc,
                       const float* __restrict__ xf, const float* __restrict__ xr,
                       const float* __restrict__ W0, const float* __restrict__ b0,
                       const float* __restrict__ W1, const float* __restrict__ b1,
                       const float* __restrict__ W2, const float* __restrict__ b2,
                       const float* __restrict__ W3, const float* __restrict__ b3,
                       const float* __restrict__ esp,
                       float* __restrict__ out)
{
    __shared__ float xs[TILE1 * SEG];        // 512 floats
    __shared__ float zsm[TILE1 * DD];        // 16KB

    const int tid = threadIdx.x;
    const int w = tid >> 5;
    const int l = tid & 31;

    const int s      = blockIdx.x & 3;
    const int chunk  = blockIdx.x >> 2;
    const int stride = gridDim.x >> 2;

    const float* Wp = (s == 0) ? W0 : (s == 1) ? W1 : (s == 2) ? W2 : W3;
    const float* bp = (s == 0) ? b0 : (s == 1) ? b1 : (s == 2) ? b2 : b3;
    const float* xp = (s == 0) ? xt : (s == 1) ? xc : (s == 2) ? xf : xr;

    // W row for d = tid: 32 contiguous floats -> 8 float4 registers
    float4 Wreg[8];
    const float4* W4 = (const float4*)(Wp + tid * SEG);
    #pragma unroll
    for (int i = 0; i < 8; i++) Wreg[i] = W4[i];
    const float bias = bp[tid];

    const float ta  = tanhf(*esp);
    const float taa = fabsf(ta);

    for (int tile = chunk; tile < TILES1; tile += stride) {
        __syncthreads();
        // stage x tile: 16 rows x 32 segs = 512 consecutive floats
        #pragma unroll
        for (int i = tid; i < TILE1 * SEG; i += 256)
            xs[i] = xp[tile * (TILE1 * SEG) + i];
        __syncthreads();

        // encode: acc[row] = b + sum_k W[d=tid][k] * x[row][k]
        float acc[TILE1];
        #pragma unroll
        for (int r = 0; r < TILE1; r++) acc[r] = bias;

        #pragma unroll
        for (int r = 0; r < TILE1; r++) {
            const float4* xr4 = (const float4*)(xs + r * SEG);
            #pragma unroll
            for (int k4 = 0; k4 < 8; k4++) {
                float4 xv = xr4[k4];
                float4 wv = Wreg[k4];
                float a = acc[r];
                a = fmaf(wv.x, xv.x, a);
                a = fmaf(wv.y, xv.y, a);
                a = fmaf(wv.z, xv.z, a);
                a = fmaf(wv.w, xv.w, a);
                acc[r] = a;
            }
        }

        #pragma unroll
        for (int r = 0; r < TILE1; r++) zsm[r * DD + tid] = acc[r];
        __syncthreads();

        // hyperbolic: warp w handles rows w and w+8 of this tile
        #pragma unroll
        for (int t = 0; t < 2; t++) {
            const int rr = w + t * 8;
            const int r  = tile * TILE1 + rr;

            float z[8];
            float lo = 0.f;
            #pragma unroll
            for (int j = 0; j < 8; j++) {
                z[j] = zsm[rr * DD + l + 32 * j];
                lo = fmaf(z[j], z[j], lo);
            }
            lo = wredsum(lo);

            float zn = sqrtf(lo);
            float n  = taa * zn;
            float s1 = ta * fminf(n, 1.5f) / fmaxf(n, 1e-8f);
            float nn = fabsf(s1) * zn;           // ||v_clipped||
            float ns = fmaxf(nn, 1e-9f);
            float sh = sinhf(nn);
            float F  = s1 * sh / ns;             // xr = F * z
            float sx = sh * nn / ns;             // ||xr||
            float x0v = sqrtf(1.f + sx * sx);    // projx time

            float* hp = out + (size_t)s * ((size_t)ROWS * DIM) + (size_t)r * DIM;
            #pragma unroll
            for (int j = 0; j < 8; j++) hp[1 + l + 32 * j] = z[j] * F;
            if (l == 0) hp[0] = x0v;
        }
    }
}

// ---------------- Kernel 2: Lorentz fusion via Gram matrix ----------------
// Warp per row. Mean stays in span{p_0..p_3}; track coefficients gam[4].
// All norms/dots are bilinear forms in the 4x4 spatial Gram matrix P.
__global__ __launch_bounds__(256)
void fusion_kernel(const float* __restrict__ lwp, float* __restrict__ out)
{
    const int w = threadIdx.x >> 5;
    const int l = threadIdx.x & 31;
    const int r = blockIdx.x * 8 + w;

    // softmax weights (per-thread, cheap)
    float lw0 = lwp[0], lw1 = lwp[1], lw2 = lwp[2], lw3 = lwp[3];
    float mxw = fmaxf(fmaxf(lw0, lw1), fmaxf(lw2, lw3));
    float e0 = expf(lw0 - mxw), e1 = expf(lw1 - mxw);
    float e2 = expf(lw2 - mxw), e3 = expf(lw3 - mxw);
    float esum = e0 + e1 + e2 + e3;
    float wgt[4] = {e0 / esum, e1 / esum, e2 / esum, e3 / esum};

    // load the 4 hyperbolic points
    float sP[4][8], tP[4];
    #pragma unroll
    for (int c = 0; c < 4; c++) {
        const float* hp = out + (size_t)c * ((size_t)ROWS * DIM) + (size_t)r * DIM;
        tP[c] = hp[0];
        #pragma unroll
        for (int j = 0; j < 8; j++) sP[c][j] = hp[1 + l + 32 * j];
    }

    // Gram matrix of spatial parts (10 unique entries, batched reductions)
    float pr[10];
    {
        int idx = 0;
        #pragma unroll
        for (int c = 0; c < 4; c++)
            #pragma unroll
            for (int d = c; d < 4; d++) {
                float lo = 0.f;
                #pragma unroll
                for (int j = 0; j < 8; j++) lo = fmaf(sP[c][j], sP[d][j], lo);
                pr[idx++] = lo;
            }
    }
    #pragma unroll
    for (int i = 0; i < 10; i++) pr[i] = wredsum(pr[i]);

    float P[4][4];
    {
        int idx = 0;
        #pragma unroll
        for (int c = 0; c < 4; c++)
            #pragma unroll
            for (int d = c; d < 4; d++) {
                P[c][d] = pr[idx];
                P[d][c] = pr[idx];
                idx++;
            }
    }
    float S[4];
    #pragma unroll
    for (int c = 0; c < 4; c++) S[c] = P[c][c];

    // ---- init: t0 = logmap(origin, p); wt = clip(sum w*t0, 2); mean = projx(expmap0(wt_sp)) ----
    float gam[4];
    float wt_t = 0.f;
    #pragma unroll
    for (int c = 0; c < 4; c++) {
        float alpha = fmaxf(tP[c], 1.0f + 1e-7f);
        float dist  = acoshf(alpha);
        float ut    = tP[c] - alpha;
        float un2   = fmaxf(S[c] - ut * ut, 1e-12f);
        float g     = dist / sqrtf(un2);
        float wg    = wgt[c] * g;
        gam[c] = wg;
        wt_t   = fmaf(wg, ut, wt_t);
    }
    float wtsp2;
    {
        float t = 0.f;
        #pragma unroll
        for (int c = 0; c < 4; c++) {
            float u = 0.f;
            #pragma unroll
            for (int d = 0; d < 4; d++) u = fmaf(gam[d], P[c][d], u);
            t = fmaf(gam[c], u, t);
        }
        wtsp2 = fmaxf(t, 0.f);
    }
    float Ssm, tm;
    {
        float nrm = sqrtf(wtsp2 + wt_t * wt_t);
        float cs  = fminf(nrm, 2.0f) / fmaxf(nrm, 1e-12f);
        float S2  = cs * cs * wtsp2;
        float nn  = sqrtf(S2);
        float ns  = fmaxf(nn, 1e-9f);
        float sh  = sinhf(nn);
        float fac = cs * sh / ns;
        #pragma unroll
        for (int c = 0; c < 4; c++) gam[c] *= fac;
        float sx = sh * nn / ns;   // ||mean spatial||
        Ssm = sx * sx;
        tm  = sqrtf(1.f + Ssm);
    }

    // ---- 5 Karcher iterations (all scalar) ----
    #pragma unroll
    for (int it = 0; it < 5; it++) {
        float dl[4];
        #pragma unroll
        for (int c = 0; c < 4; c++) {
            float t = 0.f;
            #pragma unroll
            for (int d = 0; d < 4; d++) t = fmaf(gam[d], P[d][c], t);
            dl[c] = t;
        }

        float wgv[4], utv[4];
        float A = 0.f, wv_t = 0.f;
        #pragma unroll
        for (int c = 0; c < 4; c++) {
            float alpha = fmaxf(tm * tP[c] - dl[c], 1.0f + 1e-7f);
            float dist  = acoshf(alpha);
            float ut    = tP[c] - alpha * tm;
            float U2sp  = S[c] - 2.f * alpha * dl[c] + alpha * alpha * Ssm;
            float un2   = fmaxf(U2sp - ut * ut, 1e-12f);
            float g     = dist / sqrtf(un2);
            float wg    = wgt[c] * g;
            wgv[c] = wg;
            utv[c] = ut;
            A    = fmaf(wg, alpha, A);
            wv_t = fmaf(wg, ut, wv_t);
        }

        float wvg[4];
        #pragma unroll
        for (int c = 0; c < 4; c++) wvg[c] = wgv[c] - A * gam[c];

        float wvsp2;
        {
            float t = 0.f;
            #pragma unroll
            for (int c = 0; c < 4; c++) {
                float u = 0.f;
                #pragma unroll
                for (int d = 0; d < 4; d++) u = fmaf(wvg[d], P[c][d], u);
                t = fmaf(wvg[c], u, t);
            }
            wvsp2 = fmaxf(t, 0.f);
        }

        float nrm = sqrtf(wvsp2 + wv_t * wv_t);
        float cs  = fminf(nrm, 2.0f) / fmaxf(nrm, 1e-12f);
        float q   = 0.1f * cs;
        float mk  = fmaxf(q * q * (wvsp2 - wv_t * wv_t), 1e-12f);
        float th  = sqrtf(mk);
        float ch  = coshf(th);
        float shh = sinhf(th);
        float cq  = shh * q / th;

        #pragma unroll
        for (int c = 0; c < 4; c++) gam[c] = fmaf(cq, wvg[c], ch * gam[c]);

        {
            float t = 0.f;
            #pragma unroll
            for (int c = 0; c < 4; c++) {
                float u = 0.f;
                #pragma unroll
                for (int d = 0; d < 4; d++) u = fmaf(gam[d], P[c][d], u);
                t = fmaf(gam[c], u, t);
            }
            Ssm = fmaxf(t, 0.f);
        }
        tm = sqrtf(1.f + Ssm);
    }

    // ---- write combined ----
    float* cp = out + 4 * ((size_t)ROWS * DIM) + (size_t)r * DIM;
    #pragma unroll
    for (int j = 0; j < 8; j++) {
        float v = 0.f;
        #pragma unroll
        for (int c = 0; c < 4; c++) v = fmaf(gam[c], sP[c][j], v);
        cp[1 + l + 32 * j] = v;
    }
    if (l == 0) cp[0] = tm;
}

extern "C" void kernel_launch(void* const* d_in, const int* in_sizes, int n_in,
                              void* d_out, int out_size) {
    (void)in_sizes; (void)n_in; (void)out_size;
    const float* xt = (const float*)d_in[0];
    const float* xc = (const float*)d_in[1];
    const float* xf = (const float*)d_in[2];
    const float* xr = (const float*)d_in[3];
    const float* W0 = (const float*)d_in[4];
    const float* b0 = (const float*)d_in[5];
    const float* W1 = (const float*)d_in[6];
    const float* b1 = (const float*)d_in[7];
    const float* W2 = (const float*)d_in[8];
    const float* b2 = (const float*)d_in[9];
    const float* W3 = (const float*)d_in[10];
    const float* b3 = (const float*)d_in[11];
    const float* es = (const float*)d_in[12];
    const float* lw = (const float*)d_in[13];
    float* out = (float*)d_out;

    int nsm = 148;
    cudaDeviceGetAttribute(&nsm, cudaDevAttrMultiProcessorCount, 0);
    if (nsm <= 0) nsm = 148;

    encode_hyp_kernel<<<4 * nsm, 256>>>(xt, xc, xf, xr,
                                        W0, b0, W1, b1, W2, b2, W3, b3,
                                        es, out);
    fusion_kernel<<<ROWS / 8, 256>>>(lw, out);
}

// round 3
// speedup vs baseline: 1.8394x; 1.2268x over previous
#include <cuda_runtime.h>
#include <math.h>

// Problem constants
#define BATCH    256
#define LOOKBACK 4096
#define SEG      32
#define DD       256          // embedding dim D
#define ROWS     32768        // B*N
#define DIM      257          // Lorentz dim D+1

// ---------------- packed f32x2 helpers ----------------
typedef struct __align__(16) { unsigned long long a, b; } u64x2;

__device__ __forceinline__ unsigned long long pack2(float lo, float hi) {
    unsigned long long r;
    asm("mov.b64 %0, {%1, %2};" : "=l"(r) : "f"(lo), "f"(hi));
    return r;
}
__device__ __forceinline__ void unpack2(unsigned long long v, float& lo, float& hi) {
    asm("mov.b64 {%0, %1}, %2;" : "=f"(lo), "=f"(hi) : "l"(v));
}
__device__ __forceinline__ void ffma2(unsigned long long& d,
                                      unsigned long long a, unsigned long long b) {
    asm("fma.rn.f32x2 %0, %1, %2, %0;" : "+l"(d) : "l"(a), "l"(b));
}

__device__ __forceinline__ float wredsum(float v) {
    v += __shfl_xor_sync(0xffffffffu, v, 16);
    v += __shfl_xor_sync(0xffffffffu, v, 8);
    v += __shfl_xor_sync(0xffffffffu, v, 4);
    v += __shfl_xor_sync(0xffffffffu, v, 2);
    v += __shfl_xor_sync(0xffffffffu, v, 1);
    return v;
}

// ---------------- Kernel 1: encode + hyperbolic ----------------
// One series per block (series = blockIdx.x & 3). W row for dim d=tid lives in
// 16 packed-f32x2 registers. Encode uses fma.rn.f32x2 packed over K pairs.
#define TILE1  16
#define TILES1 (ROWS / TILE1)   // 2048

__global__ __launch_bounds__(256, 2)
void encode_hyp_kernel(const float* __restrict__ xt, const float* __restrict__ xc,
                       const float* __restrict__ xf, const float* __restrict__ xr,
                       const float* __restrict__ W0, const float* __restrict__ b0,
                       const float* __restrict__ W1, const float* __restrict__ b1,
                       const float* __restrict__ W2, const float* __restrict__ b2,
                       const float* __restrict__ W3, const float* __restrict__ b3,
                       const float* __restrict__ esp,
                       float* __restrict__ out)
{
    __shared__ float xs[TILE1 * SEG];        // 2 KB
    __shared__ float zsm[TILE1 * DD];        // 16 KB

    const int tid = threadIdx.x;
    const int w = tid >> 5;
    const int l = tid & 31;

    const int s      = blockIdx.x & 3;
    const int chunk  = blockIdx.x >> 2;
    const int stride = gridDim.x >> 2;

    const float* Wp = (s == 0) ? W0 : (s == 1) ? W1 : (s == 2) ? W2 : W3;
    const float* bp = (s == 0) ? b0 : (s == 1) ? b1 : (s == 2) ? b2 : b3;
    const float* xp = (s == 0) ? xt : (s == 1) ? xc : (s == 2) ? xf : xr;

    // W row for d = tid: 32 floats -> 16 packed f32x2 (pairs over K)
    unsigned long long wp[16];
    {
        const u64x2* W16 = (const u64x2*)(Wp + tid * SEG);
        #pragma unroll
        for (int i = 0; i < 8; i++) {
            u64x2 v = W16[i];
            wp[2 * i]     = v.a;
            wp[2 * i + 1] = v.b;
        }
    }
    const float bias = bp[tid];

    const float ta  = tanhf(*esp);
    const float taa = fabsf(ta);

    for (int tile = chunk; tile < TILES1; tile += stride) {
        __syncthreads();
        #pragma unroll
        for (int i = tid; i < TILE1 * SEG; i += 256)
            xs[i] = xp[tile * (TILE1 * SEG) + i];
        __syncthreads();

        // encode with packed FMA: acc holds (even-k sum + bias, odd-k sum)
        unsigned long long acc[TILE1];
        #pragma unroll
        for (int r = 0; r < TILE1; r++) acc[r] = pack2(bias, 0.f);

        #pragma unroll
        for (int r = 0; r < TILE1; r++) {
            const u64x2* xr16 = (const u64x2*)(xs + r * SEG);
            #pragma unroll
            for (int i = 0; i < 8; i++) {
                u64x2 xv = xr16[i];              // LDS.128 broadcast
                ffma2(acc[r], wp[2 * i],     xv.a);
                ffma2(acc[r], wp[2 * i + 1], xv.b);
            }
        }

        #pragma unroll
        for (int r = 0; r < TILE1; r++) {
            float lo, hi;
            unpack2(acc[r], lo, hi);
            zsm[r * DD + tid] = lo + hi;
        }
        __syncthreads();

        // hyperbolic: warp w handles rows w and w+8 of this tile
        #pragma unroll
        for (int t = 0; t < 2; t++) {
            const int rr = w + t * 8;
            const int r  = tile * TILE1 + rr;

            float z[8];
            float lo = 0.f;
            #pragma unroll
            for (int j = 0; j < 8; j++) {
                z[j] = zsm[rr * DD + l + 32 * j];
                lo = fmaf(z[j], z[j], lo);
            }
            lo = wredsum(lo);

            float zn = sqrtf(lo);
            float n  = taa * zn;
            float s1 = ta * fminf(n, 1.5f) / fmaxf(n, 1e-8f);
            float nn = fabsf(s1) * zn;           // ||v_clipped||
            float ns = fmaxf(nn, 1e-9f);
            float sh = sinhf(nn);
            float F  = s1 * sh / ns;             // xr = F * z
            float sx = sh * nn / ns;             // ||xr||
            float x0v = sqrtf(1.f + sx * sx);    // projx time

            float* hp = out + (size_t)s * ((size_t)ROWS * DIM) + (size_t)r * DIM;
            #pragma unroll
            for (int j = 0; j < 8; j++) hp[1 + l + 32 * j] = z[j] * F;
            if (l == 0) hp[0] = x0v;
        }
    }
}

// ---------------- Kernel 2: Lorentz fusion via Gram matrix ----------------
// Block = 16 rows. Phase A: warp per 2 rows computes Gram + tP -> SMEM, sP in
// registers. Phase B: ONE warp, lane-per-row, runs the whole scalar Karcher
// recurrence (16x fewer MUFU/scalar warp-instrs). Phase C: write combined from
// register-resident sP.
#define RPB 16
#define GSTRIDE 17   // gram smem row stride (pad to dodge bank conflicts)

__global__ __launch_bounds__(256, 2)
void fusion_kernel(const float* __restrict__ lwp, float* __restrict__ out)
{
    __shared__ float gramsm[RPB * GSTRIDE];   // per row: P[10], tP[4]
    __shared__ float gout[RPB * 8];           // per row: gam[4], tm

    const int tid = threadIdx.x;
    const int w = tid >> 5;
    const int l = tid & 31;

    // softmax weights (cheap, every thread)
    float lw0 = lwp[0], lw1 = lwp[1], lw2 = lwp[2], lw3 = lwp[3];
    float mxw = fmaxf(fmaxf(lw0, lw1), fmaxf(lw2, lw3));
    float e0 = expf(lw0 - mxw), e1 = expf(lw1 - mxw);
    float e2 = expf(lw2 - mxw), e3 = expf(lw3 - mxw);
    float esum = e0 + e1 + e2 + e3;
    float wgt[4] = {e0 / esum, e1 / esum, e2 / esum, e3 / esum};

    // -------- Phase A: Gram matrices, warp w owns local rows 2w, 2w+1 --------
    float sP[2][4][8];
    #pragma unroll
    for (int t = 0; t < 2; t++) {
        const int lr = 2 * w + t;
        const int r  = blockIdx.x * RPB + lr;

        float tPl[4];
        #pragma unroll
        for (int c = 0; c < 4; c++) {
            const float* hp = out + (size_t)c * ((size_t)ROWS * DIM) + (size_t)r * DIM;
            tPl[c] = hp[0];
            #pragma unroll
            for (int j = 0; j < 8; j++) sP[t][c][j] = hp[1 + l + 32 * j];
        }

        float pr[10];
        {
            int idx = 0;
            #pragma unroll
            for (int c = 0; c < 4; c++)
                #pragma unroll
                for (int d = c; d < 4; d++) {
                    float lo = 0.f;
                    #pragma unroll
                    for (int j = 0; j < 8; j++) lo = fmaf(sP[t][c][j], sP[t][d][j], lo);
                    pr[idx++] = lo;
                }
        }
        #pragma unroll
        for (int i = 0; i < 10; i++) pr[i] = wredsum(pr[i]);

        if (l == 0) {
            #pragma unroll
            for (int i = 0; i < 10; i++) gramsm[lr * GSTRIDE + i] = pr[i];
            #pragma unroll
            for (int c = 0; c < 4; c++) gramsm[lr * GSTRIDE + 10 + c] = tPl[c];
        }
    }
    __syncthreads();

    // -------- Phase B: scalar Karcher recurrence, lane-per-row in warp 0 --------
    if (w == 0) {
        const int row = l & 15;   // lanes 16-31 duplicate (stores guarded)

        float P[4][4], tP[4];
        {
            int idx = 0;
            #pragma unroll
            for (int c = 0; c < 4; c++)
                #pragma unroll
                for (int d = c; d < 4; d++) {
                    float v = gramsm[row * GSTRIDE + idx];
                    P[c][d] = v; P[d][c] = v;
                    idx++;
                }
            #pragma unroll
            for (int c = 0; c < 4; c++) tP[c] = gramsm[row * GSTRIDE + 10 + c];
        }
        float S[4];
        #pragma unroll
        for (int c = 0; c < 4; c++) S[c] = P[c][c];

        // init: t0 = logmap(origin, p); wt = clip(sum w*t0, 2); mean
        float gam[4];
        float wt_t = 0.f;
        #pragma unroll
        for (int c = 0; c < 4; c++) {
            float alpha = fmaxf(tP[c], 1.0f + 1e-7f);
            float dist  = acoshf(alpha);
            float ut    = tP[c] - alpha;
            float un2   = fmaxf(S[c] - ut * ut, 1e-12f);
            float g     = dist / sqrtf(un2);
            float wg    = wgt[c] * g;
            gam[c] = wg;
            wt_t   = fmaf(wg, ut, wt_t);
        }
        float wtsp2;
        {
            float t = 0.f;
            #pragma unroll
            for (int c = 0; c < 4; c++) {
                float u = 0.f;
                #pragma unroll
                for (int d = 0; d < 4; d++) u = fmaf(gam[d], P[c][d], u);
                t = fmaf(gam[c], u, t);
            }
            wtsp2 = fmaxf(t, 0.f);
        }
        float Ssm, tm;
        {
            float nrm = sqrtf(wtsp2 + wt_t * wt_t);
            float cs  = fminf(nrm, 2.0f) / fmaxf(nrm, 1e-12f);
            float S2  = cs * cs * wtsp2;
            float nn  = sqrtf(S2);
            float ns  = fmaxf(nn, 1e-9f);
            float sh  = sinhf(nn);
            float fac = cs * sh / ns;
            #pragma unroll
            for (int c = 0; c < 4; c++) gam[c] *= fac;
            float sx = sh * nn / ns;
            Ssm = sx * sx;
            tm  = sqrtf(1.f + Ssm);
        }

        // 5 Karcher iterations (all scalar, vectorized over rows in lanes)
        #pragma unroll
        for (int it = 0; it < 5; it++) {
            float dl[4];
            #pragma unroll
            for (int c = 0; c < 4; c++) {
                float t = 0.f;
                #pragma unroll
                for (int d = 0; d < 4; d++) t = fmaf(gam[d], P[d][c], t);
                dl[c] = t;
            }

            float wgv[4], utv[4], alphav[4];
            float A = 0.f, wv_t = 0.f;
            #pragma unroll
            for (int c = 0; c < 4; c++) {
                float alpha = fmaxf(tm * tP[c] - dl[c], 1.0f + 1e-7f);
                float dist  = acoshf(alpha);
                float ut    = tP[c] - alpha * tm;
                float U2sp  = S[c] - 2.f * alpha * dl[c] + alpha * alpha * Ssm;
                float un2   = fmaxf(U2sp - ut * ut, 1e-12f);
                float g     = dist / sqrtf(un2);
                float wg    = wgt[c] * g;
                wgv[c] = wg; utv[c] = ut; alphav[c] = alpha;
                A    = fmaf(wg, alpha, A);
                wv_t = fmaf(wg, ut, wv_t);
            }

            float wvg[4];
            #pragma unroll
            for (int c = 0; c < 4; c++) wvg[c] = wgv[c] - A * gam[c];

            float wvsp2;
            {
                float t = 0.f;
                #pragma unroll
                for (int c = 0; c < 4; c++) {
                    float u = 0.f;
                    #pragma unroll
                    for (int d = 0; d < 4; d++) u = fmaf(wvg[d], P[c][d], u);
                    t = fmaf(wvg[c], u, t);
                }
                wvsp2 = fmaxf(t, 0.f);
            }

            float nrm = sqrtf(wvsp2 + wv_t * wv_t);
            float cs  = fminf(nrm, 2.0f) / fmaxf(nrm, 1e-12f);
            float q   = 0.1f * cs;
            float mk  = fmaxf(q * q * (wvsp2 - wv_t * wv_t), 1e-12f);
            float th  = sqrtf(mk);
            float ch  = coshf(th);
            float shh = sinhf(th);
            float cq  = shh * q / th;

            #pragma unroll
            for (int c = 0; c < 4; c++) gam[c] = fmaf(cq, wvg[c], ch * gam[c]);

            {
                float t = 0.f;
                #pragma unroll
                for (int c = 0; c < 4; c++) {
                    float u = 0.f;
                    #pragma unroll
                    for (int d = 0; d < 4; d++) u = fmaf(gam[d], P[c][d], u);
                    t = fmaf(gam[c], u, t);
                }
                Ssm = fmaxf(t, 0.f);
            }
            tm = sqrtf(1.f + Ssm);
        }

        if (l < 16) {
            #pragma unroll
            for (int c = 0; c < 4; c++) gout[row * 8 + c] = gam[c];
            gout[row * 8 + 4] = tm;
        }
    }
    __syncthreads();

    // -------- Phase C: write combined from register-resident sP --------
    #pragma unroll
    for (int t = 0; t < 2; t++) {
        const int lr = 2 * w + t;
        const int r  = blockIdx.x * RPB + lr;

        float g0 = gout[lr * 8 + 0], g1 = gout[lr * 8 + 1];
        float g2 = gout[lr * 8 + 2], g3 = gout[lr * 8 + 3];
        float tm = gout[lr * 8 + 4];

        float* cp = out + 4 * ((size_t)ROWS * DIM) + (size_t)r * DIM;
        #pragma unroll
        for (int j = 0; j < 8; j++) {
            float v = g0 * sP[t][0][j];
            v = fmaf(g1, sP[t][1][j], v);
            v = fmaf(g2, sP[t][2][j], v);
            v = fmaf(g3, sP[t][3][j], v);
            cp[1 + l + 32 * j] = v;
        }
        if (l == 0) cp[0] = tm;
    }
}

extern "C" void kernel_launch(void* const* d_in, const int* in_sizes, int n_in,
                              void* d_out, int out_size) {
    (void)in_sizes; (void)n_in; (void)out_size;
    const float* xt = (const float*)d_in[0];
    const float* xc = (const float*)d_in[1];
    const float* xf = (const float*)d_in[2];
    const float* xr = (const float*)d_in[3];
    const float* W0 = (const float*)d_in[4];
    const float* b0 = (const float*)d_in[5];
    const float* W1 = (const float*)d_in[6];
    const float* b1 = (const float*)d_in[7];
    const float* W2 = (const float*)d_in[8];
    const float* b2 = (const float*)d_in[9];
    const float* W3 = (const float*)d_in[10];
    const float* b3 = (const float*)d_in[11];
    const float* es = (const float*)d_in[12];
    const float* lw = (const float*)d_in[13];
    float* out = (float*)d_out;

    int nsm = 148;
    cudaDeviceGetAttribute(&nsm, cudaDevAttrMultiProcessorCount, 0);
    if (nsm <= 0) nsm = 148;

    encode_hyp_kernel<<<8 * nsm, 256>>>(xt, xc, xf, xr,
                                        W0, b0, W1, b1, W2, b2, W3, b3,
                                        es, out);
    fusion_kernel<<<ROWS / RPB, 256>>>(lw, out);
}